// round 14
// baseline (speedup 1.0000x reference)
#include <cuda_runtime.h>
#include <cstdint>
#include <cstddef>

#define Mdim 256
#define Ndim 1024
#define Bdim 16384
#define Kiter 16
#define Pk 50u

// ---------------------------------------------------------------------------
// Scratch (allocation-free __device__ globals). Batch-major layout.
// Big tensors fp32; small constant matrices pre-split into tf32 hi/lo.
// ---------------------------------------------------------------------------
__device__ float g_x [(size_t)Bdim * Ndim];      // x (B,N)
__device__ float g_r [(size_t)Bdim * Mdim];      // r (B,M)
__device__ float g_c [(size_t)Bdim * Ndim];      // c (B,N)
__device__ float g_phihi[(size_t)Mdim * Ndim];   // phi (M,N), k=n contiguous
__device__ float g_philo[(size_t)Mdim * Ndim];
__device__ float g_wthi [(size_t)Ndim * Mdim];   // W^T (N,M), k=m contiguous
__device__ float g_wtlo [(size_t)Ndim * Mdim];

// ---------------------------------------------------------------------------
// PTX helpers (plain-sm_103-legal: cp.async sm_80+, mma.sync tf32 sm_80+)
// ---------------------------------------------------------------------------
__device__ __forceinline__ void cp_async16(uint32_t saddr, const void* gaddr) {
    asm volatile("cp.async.cg.shared.global [%0], [%1], 16;\n"
                 :: "r"(saddr), "l"(gaddr));
}
#define CP_COMMIT() asm volatile("cp.async.commit_group;\n" ::: "memory")
#define CP_WAIT0()  asm volatile("cp.async.wait_group 0;\n" ::: "memory")
#define CP_WAIT1()  asm volatile("cp.async.wait_group 1;\n" ::: "memory")

__device__ __forceinline__ void split_tf32(float v, uint32_t& hi, uint32_t& lo) {
    uint32_t h;
    asm("cvt.rna.tf32.f32 %0, %1;" : "=r"(h) : "f"(v));
    float hf = __uint_as_float(h);
    asm("cvt.rna.tf32.f32 %0, %1;" : "=r"(lo) : "f"(v - hf));
    hi = h;
}

__device__ __forceinline__ void split_tf32f(float v, float& hi, float& lo) {
    uint32_t h, l;
    split_tf32(v, h, l);
    hi = __uint_as_float(h);
    lo = __uint_as_float(l);
}

__device__ __forceinline__ void mma_tf32(float* d, const uint32_t* a,
                                         const uint32_t* b) {
    asm volatile(
        "mma.sync.aligned.m16n8k8.row.col.f32.tf32.tf32.f32 "
        "{%0,%1,%2,%3}, {%4,%5,%6,%7}, {%8,%9}, {%0,%1,%2,%3};"
        : "+f"(d[0]), "+f"(d[1]), "+f"(d[2]), "+f"(d[3])
        : "r"(a[0]), "r"(a[1]), "r"(a[2]), "r"(a[3]),
          "r"(b[0]), "r"(b[1]));
}

// ---------------------------------------------------------------------------
// TF32x3 GEMM: D(B x Nrows) = A(B,Kd) @ (Bhi+Blo)(Nrows,Kd)^T [- Sub if SUBY]
// A fp32, cvt-split to tf32 hi/lo in registers at fragment load.
// B pre-split in global (constant matrices; L2-resident).
// Tile 128(b) x 128(n) x 32(k), 256 threads (2x4 warps), warp tile 64x32.
// Term-major MMA order. R10 two-barrier protocol, HALF the barrier count
// of the KTILE=16 version (4 inner k-steps per synchronization epoch).
// ---------------------------------------------------------------------------
#define KTILE 32
#define ROWPAD 36
#define OPF (128 * ROWPAD)                   // 4608 floats per operand tile
#define STAGE_FLOATS (3 * OPF)               // A, Bhi, Blo
#define STAGE_BYTES (STAGE_FLOATS * 4)       // 55296 B
#define GEMM_SMEM (2 * STAGE_BYTES)          // 110592 B

template<int SUBY>
__global__ void __launch_bounds__(256)
gemm_tc(const float* __restrict__ A,
        const float* __restrict__ Bhi, const float* __restrict__ Blo,
        float* __restrict__ D, const float* __restrict__ Sub,
        int Kd, int CStride)
{
    extern __shared__ float sm[];
    const int tid  = threadIdx.x;
    const int wid  = tid >> 5;
    const int lane = tid & 31;
    const int gid  = lane >> 2;
    const int tig  = lane & 3;
    const int wm   = wid >> 2;       // 0..1 -> 64-row strip (batch)
    const int wn   = wid & 3;        // 0..3 -> 32-col strip (n)
    const int b0   = blockIdx.y * 128;
    const int n0   = blockIdx.x * 128;
    const uint32_t smbase = (uint32_t)__cvta_generic_to_shared(sm);

    float acc[4][4][4];
#pragma unroll
    for (int i = 0; i < 4; i++)
#pragma unroll
        for (int j = 0; j < 4; j++)
#pragma unroll
            for (int q = 0; q < 4; q++) acc[i][j][q] = 0.0f;

    // Stage loader: 3 ops x 128 rows x 8 chunks(16B) = 3072; 12/thread.
    auto load_stage = [&](int t, int buf) {
        const int k0 = t * KTILE;
        const uint32_t sb = smbase + buf * STAGE_BYTES;
#pragma unroll
        for (int l = 0; l < 12; l++) {
            int idx = tid + l * 256;           // 0..3071
            int op  = idx >> 10;               // 0..2
            int rem = idx & 1023;
            int row = rem >> 3;                // 0..127
            int ch  = rem & 7;                 // 0..7
            uint32_t so = (op * OPF + row * ROWPAD + ch * 4) * 4;
            const float* src;
            if (op == 0)      src = A   + (size_t)(b0 + row) * Kd;
            else if (op == 1) src = Bhi + (size_t)(n0 + row) * Kd;
            else              src = Blo + (size_t)(n0 + row) * Kd;
            cp_async16(sb + so, src + k0 + ch * 4);
        }
    };

    const int T = Kd / KTILE;
    load_stage(0, 0);
    CP_COMMIT();

    for (int t = 0; t < T; t++) {
        const int buf = t & 1;
        if (t + 1 < T) {
            load_stage(t + 1, buf ^ 1);
            CP_COMMIT();
            CP_WAIT1();
        } else {
            CP_WAIT0();
        }
        __syncthreads();

        const float* As = sm + buf * STAGE_FLOATS;
        const float* Bh = As + OPF;
        const float* Bl = Bh + OPF;

#pragma unroll
        for (int s = 0; s < 4; s++) {
            const int kb = s * 8;
            uint32_t bhi[4][2], blo[4][2];
#pragma unroll
            for (int nt = 0; nt < 4; nt++) {
                int n = wn * 32 + nt * 8 + gid;
                bhi[nt][0] = __float_as_uint(Bh[n * ROWPAD + kb + tig]);
                bhi[nt][1] = __float_as_uint(Bh[n * ROWPAD + kb + tig + 4]);
                blo[nt][0] = __float_as_uint(Bl[n * ROWPAD + kb + tig]);
                blo[nt][1] = __float_as_uint(Bl[n * ROWPAD + kb + tig + 4]);
            }
#pragma unroll
            for (int mt = 0; mt < 4; mt++) {
                int m = wm * 64 + mt * 16 + gid;
                uint32_t ahi[4], alo[4];
                split_tf32(As[m * ROWPAD + kb + tig], ahi[0], alo[0]);
                split_tf32(As[(m + 8) * ROWPAD + kb + tig], ahi[1], alo[1]);
                split_tf32(As[m * ROWPAD + kb + tig + 4], ahi[2], alo[2]);
                split_tf32(As[(m + 8) * ROWPAD + kb + tig + 4], ahi[3], alo[3]);
                // term-major: consecutive MMAs touch different accumulators
#pragma unroll
                for (int nt = 0; nt < 4; nt++)
                    mma_tf32(acc[mt][nt], ahi, bhi[nt]);
#pragma unroll
                for (int nt = 0; nt < 4; nt++)
                    mma_tf32(acc[mt][nt], ahi, blo[nt]);
#pragma unroll
                for (int nt = 0; nt < 4; nt++)
                    mma_tf32(acc[mt][nt], alo, bhi[nt]);
            }
        }
        __syncthreads();
    }

    // Epilogue. Fragment: c0:(r,2c) c1:(r,2c+1) c2:(r+8,2c) c3:(r+8,2c+1)
#pragma unroll
    for (int mt = 0; mt < 4; mt++) {
        int r0 = b0 + wm * 64 + mt * 16 + gid;
#pragma unroll
        for (int nt = 0; nt < 4; nt++) {
            int col = n0 + wn * 32 + nt * 8 + tig * 2;
            float2 v0 = make_float2(acc[mt][nt][0], acc[mt][nt][1]);
            float2 v1 = make_float2(acc[mt][nt][2], acc[mt][nt][3]);
            if (SUBY) {
                float2 y0 = *(const float2*)(Sub + (size_t)r0 * CStride + col);
                float2 y1 = *(const float2*)(Sub + (size_t)(r0 + 8) * CStride + col);
                v0.x -= y0.x; v0.y -= y0.y;
                v1.x -= y1.x; v1.y -= y1.y;
            }
            *(float2*)(D + (size_t)r0 * CStride + col) = v0;
            *(float2*)(D + (size_t)(r0 + 8) * CStride + col) = v1;
        }
    }
}

// ---------------------------------------------------------------------------
// Fused update on (B,N): one warp per batch row (R10-proven smem version).
// v = x - gamma*c; thr = exact Pk-th largest |v| (4-pass radix select on fp32
// bits); xout = (|v|>thr) ? v : soft(v, theta*g(|x|)).
// ---------------------------------------------------------------------------
__global__ void __launch_bounds__(256)
update_kernel(const float* __restrict__ x, float* __restrict__ xout,
              const float* __restrict__ c,
              const float* __restrict__ gammaArr,
              const float* __restrict__ thetaArr, int it)
{
    __shared__ float    v[8][1024];
    __shared__ unsigned hist[8][256];

    const int tid  = threadIdx.x;
    const int w    = tid >> 5;
    const int lane = tid & 31;
    const size_t base = ((size_t)blockIdx.x * 8 + w) * Ndim;
    const float gamma = gammaArr[it];
    const float theta = thetaArr[it];

    float xabs[32];
#pragma unroll
    for (int i = 0; i < 8; i++) {
        int n = i * 128 + lane * 4;
        float4 xv = *(const float4*)(x + base + n);
        float4 cc = *(const float4*)(c + base + n);
        xabs[i * 4 + 0] = fabsf(xv.x);
        xabs[i * 4 + 1] = fabsf(xv.y);
        xabs[i * 4 + 2] = fabsf(xv.z);
        xabs[i * 4 + 3] = fabsf(xv.w);
        float4 vv;
        vv.x = xv.x - gamma * cc.x;
        vv.y = xv.y - gamma * cc.y;
        vv.z = xv.z - gamma * cc.z;
        vv.w = xv.w - gamma * cc.w;
        *(float4*)(&v[w][n]) = vv;
    }
    __syncwarp();

    unsigned prefix = 0u, mask = 0u, k = Pk;
    unsigned* h = hist[w];
#pragma unroll
    for (int pass = 0; pass < 4; pass++) {
        const int shift = 24 - 8 * pass;
#pragma unroll
        for (int i = lane; i < 256; i += 32) h[i] = 0u;
        __syncwarp();
        for (int n = lane; n < 1024; n += 32) {
            unsigned e = __float_as_uint(v[w][n]) & 0x7FFFFFFFu;
            if ((e & mask) == prefix)
                atomicAdd(&h[(e >> shift) & 0xFFu], 1u);
        }
        __syncwarp();
        unsigned loc[8];
        unsigned s = 0u;
#pragma unroll
        for (int r = 7; r >= 0; r--) { s += h[lane * 8 + r]; loc[r] = s; }
        unsigned inc = s;
#pragma unroll
        for (int off = 1; off < 32; off <<= 1) {
            unsigned t = __shfl_down_sync(0xffffffffu, inc, off);
            if (lane + off < 32) inc += t;
        }
        const unsigned above = inc - s;
        unsigned dfound = 0u, kfound = 0u;
        bool found = false;
#pragma unroll
        for (int r = 7; r >= 0; r--) {
            unsigned cge  = above + loc[r];
            unsigned cge1 = above + (r < 7 ? loc[r + 1] : 0u);
            if (cge >= k && cge1 < k) {
                dfound = (unsigned)(lane * 8 + r);
                kfound = k - cge1;
                found = true;
            }
        }
        unsigned bal = __ballot_sync(0xffffffffu, found);
        int src = __ffs(bal) - 1;
        dfound = __shfl_sync(0xffffffffu, dfound, src);
        kfound = __shfl_sync(0xffffffffu, kfound, src);
        k = kfound;
        prefix |= dfound << shift;
        mask   |= 0xFFu << shift;
        __syncwarp();
    }
    const float thrv = __uint_as_float(prefix);

#pragma unroll
    for (int i = 0; i < 8; i++) {
        int n = i * 128 + lane * 4;
        float4 vv = *(const float4*)(&v[w][n]);
        float4 o;
        float* vp = &vv.x;
        float* op = &o.x;
#pragma unroll
        for (int jc = 0; jc < 4; jc++) {
            float val = vp[jc];
            float av = fabsf(val);
            float th = theta * (1.0f / (xabs[i * 4 + jc] / 0.1f + 1.0f));
            float st = copysignf(fmaxf(av - th, 0.0f), val);
            op[jc] = (av > thrv) ? val : st;
        }
        *(float4*)(xout + base + n) = o;
    }
}

// ---------------------------------------------------------------------------
// Prep / misc kernels
// ---------------------------------------------------------------------------
__global__ void split_kernel(const float* __restrict__ in, float* __restrict__ hi,
                             float* __restrict__ lo, size_t n)
{
    for (size_t i = (size_t)blockIdx.x * blockDim.x + threadIdx.x; i < n;
         i += (size_t)gridDim.x * blockDim.x) {
        float h, l;
        split_tf32f(in[i], h, l);
        hi[i] = h;
        lo[i] = l;
    }
}

__global__ void transpose_split_kernel(const float* __restrict__ Win,
                                       float* __restrict__ wthi,
                                       float* __restrict__ wtlo)
{
    __shared__ float tile[32][33];
    int n0 = blockIdx.x * 32;
    int m0 = blockIdx.y * 32;
    int tx = threadIdx.x, ty = threadIdx.y;
    for (int i = ty; i < 32; i += 8)
        tile[i][tx] = Win[(size_t)(m0 + i) * Ndim + n0 + tx];
    __syncthreads();
    for (int i = ty; i < 32; i += 8) {
        float h, l;
        split_tf32f(tile[tx][i], h, l);
        size_t o = (size_t)(n0 + i) * Mdim + m0 + tx;
        wthi[o] = h;
        wtlo[o] = l;
    }
}

__global__ void neg_copy_kernel(const float* __restrict__ src,
                                float* __restrict__ dst, size_t n)
{
    size_t i = ((size_t)blockIdx.x * blockDim.x + threadIdx.x) * 4;
    if (i < n) {
        float4 vq = *(const float4*)(src + i);
        vq.x = -vq.x; vq.y = -vq.y; vq.z = -vq.z; vq.w = -vq.w;
        *(float4*)(dst + i) = vq;
    }
}

__global__ void zero_kernel(float* __restrict__ p, size_t n)
{
    for (size_t i = (size_t)blockIdx.x * blockDim.x + threadIdx.x; i < n;
         i += (size_t)gridDim.x * blockDim.x)
        p[i] = 0.0f;
}

// ---------------------------------------------------------------------------
// Launch
// ---------------------------------------------------------------------------
extern "C" void kernel_launch(void* const* d_in, const int* in_sizes, int n_in,
                              void* d_out, int out_size)
{
    const float* y     = (const float*)d_in[0];
    const float* phi   = (const float*)d_in[1];
    const float* W     = (const float*)d_in[2];
    const float* gamma = (const float*)d_in[3];
    const float* theta = (const float*)d_in[4];
    float* out = (float*)d_out;

    float *xp, *rp, *cp, *phihi, *philo, *wthi, *wtlo;
    cudaGetSymbolAddress((void**)&xp,    g_x);
    cudaGetSymbolAddress((void**)&rp,    g_r);
    cudaGetSymbolAddress((void**)&cp,    g_c);
    cudaGetSymbolAddress((void**)&phihi, g_phihi);
    cudaGetSymbolAddress((void**)&philo, g_philo);
    cudaGetSymbolAddress((void**)&wthi,  g_wthi);
    cudaGetSymbolAddress((void**)&wtlo,  g_wtlo);

    cudaFuncSetAttribute(gemm_tc<1>, cudaFuncAttributeMaxDynamicSharedMemorySize,
                         GEMM_SMEM);
    cudaFuncSetAttribute(gemm_tc<0>, cudaFuncAttributeMaxDynamicSharedMemorySize,
                         GEMM_SMEM);

    split_kernel<<<512, 256>>>(phi, phihi, philo, (size_t)Mdim * Ndim);
    transpose_split_kernel<<<dim3(Ndim / 32, Mdim / 32), dim3(32, 8)>>>(W, wthi, wtlo);
    zero_kernel<<<2048, 256>>>(xp, (size_t)Bdim * Ndim);

    for (int it = 0; it < Kiter; it++) {
        // r = x @ phi^T - y  (it 0: x = 0 -> r = -y)
        if (it == 0) {
            neg_copy_kernel<<<(Bdim * Mdim / 4 + 255) / 256, 256>>>(
                y, rp, (size_t)Bdim * Mdim);
        } else {
            gemm_tc<1><<<dim3(Mdim / 128, Bdim / 128), 256, GEMM_SMEM>>>(
                xp, phihi, philo, rp, y, Ndim, Mdim);
        }
        // c = r @ W  (B operand = W^T pre-split, k-major over M)
        gemm_tc<0><<<dim3(Ndim / 128, Bdim / 128), 256, GEMM_SMEM>>>(
            rp, wthi, wtlo, cp, nullptr, Mdim, Ndim);
        // x = soft_threshold(x - gamma*c, theta*g(|x|), 50)
        float* xout = (it == Kiter - 1) ? out : xp;
        update_kernel<<<Bdim / 8, 256>>>(xp, xout, cp, gamma, theta, it);
    }

    // zero the tail (the two (K,1) zero outputs appended after x)
    long long tail = (long long)out_size - (long long)Ndim * Bdim;
    if (tail > 0)
        zero_kernel<<<1, 256>>>(out + (size_t)Ndim * Bdim, (size_t)tail);
}

// round 16
// speedup vs baseline: 1.4355x; 1.4355x over previous
#include <cuda_runtime.h>
#include <cuda_fp16.h>
#include <cstdint>
#include <cstddef>

#define Mdim 256
#define Ndim 1024
#define Bdim 16384
#define Kiter 16
#define Pk 50u

// ---------------------------------------------------------------------------
// Scratch (allocation-free __device__ globals). Batch-major layout.
// Big tensors fp32; constant matrices pre-split into PACKED half2 hi/lo.
// ---------------------------------------------------------------------------
__device__ float    g_x [(size_t)Bdim * Ndim];       // x (B,N)
__device__ float    g_r [(size_t)Bdim * Mdim];       // r (B,M)
__device__ float    g_c [(size_t)Bdim * Ndim];       // c (B,N); head reused as W^T fp32 temp during prep
__device__ uint32_t g_phih2[(size_t)Mdim * Ndim / 2]; // phi hi, half2-packed along k=n
__device__ uint32_t g_phil2[(size_t)Mdim * Ndim / 2]; // phi lo
__device__ uint32_t g_wth2 [(size_t)Ndim * Mdim / 2]; // W^T hi, packed along k=m
__device__ uint32_t g_wtl2 [(size_t)Ndim * Mdim / 2]; // W^T lo

// ---------------------------------------------------------------------------
// PTX helpers (plain-sm_103-legal: cp.async sm_80+, mma.sync f16 sm_80+)
// ---------------------------------------------------------------------------
__device__ __forceinline__ void cp_async16(uint32_t saddr, const void* gaddr) {
    asm volatile("cp.async.cg.shared.global [%0], [%1], 16;\n"
                 :: "r"(saddr), "l"(gaddr));
}
#define CP_COMMIT() asm volatile("cp.async.commit_group;\n" ::: "memory")
#define CP_WAIT0()  asm volatile("cp.async.wait_group 0;\n" ::: "memory")
#define CP_WAIT1()  asm volatile("cp.async.wait_group 1;\n" ::: "memory")

// fp16 split of a float2 pair: hi = rn(v) packed half2, lo = rn(v - hi) packed.
// Missing cross term in 3-product GEMM ~ 2^-22 relative.
__device__ __forceinline__ void h2split(float2 v, uint32_t& hi, uint32_t& lo) {
    __half2 h = __floats2half2_rn(v.x, v.y);
    float2 hf = __half22float2(h);
    __half2 l = __floats2half2_rn(v.x - hf.x, v.y - hf.y);
    hi = *reinterpret_cast<uint32_t*>(&h);
    lo = *reinterpret_cast<uint32_t*>(&l);
}

__device__ __forceinline__ void mma_f16(float* d, const uint32_t* a,
                                        const uint32_t* b) {
    asm volatile(
        "mma.sync.aligned.m16n8k16.row.col.f32.f16.f16.f32 "
        "{%0,%1,%2,%3}, {%4,%5,%6,%7}, {%8,%9}, {%0,%1,%2,%3};"
        : "+f"(d[0]), "+f"(d[1]), "+f"(d[2]), "+f"(d[3])
        : "r"(a[0]), "r"(a[1]), "r"(a[2]), "r"(a[3]),
          "r"(b[0]), "r"(b[1]));
}

// ---------------------------------------------------------------------------
// FP16x3 GEMM: D(B x Nrows) = A(B,Kd) @ (Bhi+Blo)(Nrows,Kd)^T [- Sub if SUBY]
// A fp32 in smem, split to half2 hi/lo in registers at fragment load.
// B pre-split PACKED half2 in global (constants; L2-resident) -> pure LDS.
// Tile 128(b) x 128(n) x 16(k), 256 threads (2x4 warps), warp tile 64x32.
// One m16n8k16 fragment set covers the whole k-tile; 48 MMAs/warp/tile.
// Term-major MMA order. R10 two-barrier pipeline protocol.
// BROWPAD=12 uint32 (48B) keeps every cp.async smem target 16B-aligned.
// ---------------------------------------------------------------------------
#define KTILE 16
#define AROWPAD 20                           // fp32 per A row (16 used), 80B
#define BROWPAD 12                           // uint32 per B row (8 used), 48B
#define ABYTES (128 * AROWPAD * 4)           // 10240
#define BBYTES (128 * BROWPAD * 4)           // 6144
#define STAGE_BYTES (ABYTES + 2 * BBYTES)    // 22528
#define GEMM_SMEM (2 * STAGE_BYTES)          // 45056

template<int SUBY>
__global__ void __launch_bounds__(256)
gemm_tc(const float* __restrict__ A,
        const uint32_t* __restrict__ Bh2, const uint32_t* __restrict__ Bl2,
        float* __restrict__ D, const float* __restrict__ Sub,
        int Kd, int CStride)
{
    extern __shared__ float sm[];
    const int tid  = threadIdx.x;
    const int wid  = tid >> 5;
    const int lane = tid & 31;
    const int gid  = lane >> 2;
    const int tig  = lane & 3;
    const int wm   = wid >> 2;       // 0..1 -> 64-row strip (batch)
    const int wn   = wid & 3;        // 0..3 -> 32-col strip (n)
    const int b0   = blockIdx.y * 128;
    const int n0   = blockIdx.x * 128;
    const uint32_t smbase = (uint32_t)__cvta_generic_to_shared(sm);
    const int Kh = Kd >> 1;          // packed half2 row stride for B

    float acc[4][4][4];
#pragma unroll
    for (int i = 0; i < 4; i++)
#pragma unroll
        for (int j = 0; j < 4; j++)
#pragma unroll
            for (int q = 0; q < 4; q++) acc[i][j][q] = 0.0f;

    // Stage loader: A 512 chunks (2/thr), Bh 256 (1/thr), Bl 256 (1/thr).
    auto load_stage = [&](int t, int buf) {
        const int k0 = t * KTILE;
        const uint32_t sb = smbase + buf * STAGE_BYTES;
#pragma unroll
        for (int l = 0; l < 2; l++) {
            int idx = tid + l * 256;           // 0..511
            int row = idx >> 2;                // 0..127
            int ch  = idx & 3;                 // 0..3
            cp_async16(sb + (row * AROWPAD + ch * 4) * 4,
                       A + (size_t)(b0 + row) * Kd + k0 + ch * 4);
        }
        {
            int row = tid >> 1;                // 0..127
            int ch  = tid & 1;                 // 0..1 (two 16B chunks per row)
            uint32_t so = (row * BROWPAD + ch * 4) * 4;
            cp_async16(sb + ABYTES + so,
                       Bh2 + (size_t)(n0 + row) * Kh + (k0 >> 1) + ch * 4);
            cp_async16(sb + ABYTES + BBYTES + so,
                       Bl2 + (size_t)(n0 + row) * Kh + (k0 >> 1) + ch * 4);
        }
    };

    const int T = Kd / KTILE;
    load_stage(0, 0);
    CP_COMMIT();

    for (int t = 0; t < T; t++) {
        const int buf = t & 1;
        if (t + 1 < T) {
            load_stage(t + 1, buf ^ 1);
            CP_COMMIT();
            CP_WAIT1();
        } else {
            CP_WAIT0();
        }
        __syncthreads();

        const float*    As = sm + buf * (STAGE_BYTES / 4);
        const uint32_t* Bh = (const uint32_t*)(As + ABYTES / 4);
        const uint32_t* Bl = Bh + BBYTES / 4;

        // B fragments: b0 = k pair (2tig,2tig+1), b1 = k pair (+8); col gid
        uint32_t bhi[4][2], blo[4][2];
#pragma unroll
        for (int nt = 0; nt < 4; nt++) {
            int n = wn * 32 + nt * 8 + gid;
            bhi[nt][0] = Bh[n * BROWPAD + tig];
            bhi[nt][1] = Bh[n * BROWPAD + tig + 4];
            blo[nt][0] = Bl[n * BROWPAD + tig];
            blo[nt][1] = Bl[n * BROWPAD + tig + 4];
        }
#pragma unroll
        for (int mt = 0; mt < 4; mt++) {
            int m = wm * 64 + mt * 16 + gid;
            // a0:(m,2tig..) a1:(m+8,2tig..) a2:(m,2tig+8..) a3:(m+8,2tig+8..)
            float2 v0 = *(const float2*)&As[m * AROWPAD + 2 * tig];
            float2 v1 = *(const float2*)&As[(m + 8) * AROWPAD + 2 * tig];
            float2 v2 = *(const float2*)&As[m * AROWPAD + 2 * tig + 8];
            float2 v3 = *(const float2*)&As[(m + 8) * AROWPAD + 2 * tig + 8];
            uint32_t ahi[4], alo[4];
            h2split(v0, ahi[0], alo[0]);
            h2split(v1, ahi[1], alo[1]);
            h2split(v2, ahi[2], alo[2]);
            h2split(v3, ahi[3], alo[3]);
            // term-major: consecutive MMAs touch different accumulators
#pragma unroll
            for (int nt = 0; nt < 4; nt++)
                mma_f16(acc[mt][nt], ahi, bhi[nt]);
#pragma unroll
            for (int nt = 0; nt < 4; nt++)
                mma_f16(acc[mt][nt], ahi, blo[nt]);
#pragma unroll
            for (int nt = 0; nt < 4; nt++)
                mma_f16(acc[mt][nt], alo, bhi[nt]);
        }
        __syncthreads();
    }

    // Epilogue. Fragment: c0:(r,2c) c1:(r,2c+1) c2:(r+8,2c) c3:(r+8,2c+1)
#pragma unroll
    for (int mt = 0; mt < 4; mt++) {
        int r0 = b0 + wm * 64 + mt * 16 + gid;
#pragma unroll
        for (int nt = 0; nt < 4; nt++) {
            int col = n0 + wn * 32 + nt * 8 + tig * 2;
            float2 v0 = make_float2(acc[mt][nt][0], acc[mt][nt][1]);
            float2 v1 = make_float2(acc[mt][nt][2], acc[mt][nt][3]);
            if (SUBY) {
                float2 y0 = *(const float2*)(Sub + (size_t)r0 * CStride + col);
                float2 y1 = *(const float2*)(Sub + (size_t)(r0 + 8) * CStride + col);
                v0.x -= y0.x; v0.y -= y0.y;
                v1.x -= y1.x; v1.y -= y1.y;
            }
            *(float2*)(D + (size_t)r0 * CStride + col) = v0;
            *(float2*)(D + (size_t)(r0 + 8) * CStride + col) = v1;
        }
    }
}

// ---------------------------------------------------------------------------
// Fused update on (B,N): one warp per batch row (R10-proven).
// v = x - gamma*c; thr = exact Pk-th largest |v| (4-pass radix select on fp32
// bits); xout = (|v|>thr) ? v : soft(v, theta*g(|x|)).
// ---------------------------------------------------------------------------
__global__ void __launch_bounds__(256)
update_kernel(const float* __restrict__ x, float* __restrict__ xout,
              const float* __restrict__ c,
              const float* __restrict__ gammaArr,
              const float* __restrict__ thetaArr, int it)
{
    __shared__ float    v[8][1024];
    __shared__ unsigned hist[8][256];

    const int tid  = threadIdx.x;
    const int w    = tid >> 5;
    const int lane = tid & 31;
    const size_t base = ((size_t)blockIdx.x * 8 + w) * Ndim;
    const float gamma = gammaArr[it];
    const float theta = thetaArr[it];

    float xabs[32];
#pragma unroll
    for (int i = 0; i < 8; i++) {
        int n = i * 128 + lane * 4;
        float4 xv = *(const float4*)(x + base + n);
        float4 cc = *(const float4*)(c + base + n);
        xabs[i * 4 + 0] = fabsf(xv.x);
        xabs[i * 4 + 1] = fabsf(xv.y);
        xabs[i * 4 + 2] = fabsf(xv.z);
        xabs[i * 4 + 3] = fabsf(xv.w);
        float4 vv;
        vv.x = xv.x - gamma * cc.x;
        vv.y = xv.y - gamma * cc.y;
        vv.z = xv.z - gamma * cc.z;
        vv.w = xv.w - gamma * cc.w;
        *(float4*)(&v[w][n]) = vv;
    }
    __syncwarp();

    unsigned prefix = 0u, mask = 0u, k = Pk;
    unsigned* h = hist[w];
#pragma unroll
    for (int pass = 0; pass < 4; pass++) {
        const int shift = 24 - 8 * pass;
#pragma unroll
        for (int i = lane; i < 256; i += 32) h[i] = 0u;
        __syncwarp();
        for (int n = lane; n < 1024; n += 32) {
            unsigned e = __float_as_uint(v[w][n]) & 0x7FFFFFFFu;
            if ((e & mask) == prefix)
                atomicAdd(&h[(e >> shift) & 0xFFu], 1u);
        }
        __syncwarp();
        unsigned loc[8];
        unsigned s = 0u;
#pragma unroll
        for (int r = 7; r >= 0; r--) { s += h[lane * 8 + r]; loc[r] = s; }
        unsigned inc = s;
#pragma unroll
        for (int off = 1; off < 32; off <<= 1) {
            unsigned t = __shfl_down_sync(0xffffffffu, inc, off);
            if (lane + off < 32) inc += t;
        }
        const unsigned above = inc - s;
        unsigned dfound = 0u, kfound = 0u;
        bool found = false;
#pragma unroll
        for (int r = 7; r >= 0; r--) {
            unsigned cge  = above + loc[r];
            unsigned cge1 = above + (r < 7 ? loc[r + 1] : 0u);
            if (cge >= k && cge1 < k) {
                dfound = (unsigned)(lane * 8 + r);
                kfound = k - cge1;
                found = true;
            }
        }
        unsigned bal = __ballot_sync(0xffffffffu, found);
        int src = __ffs(bal) - 1;
        dfound = __shfl_sync(0xffffffffu, dfound, src);
        kfound = __shfl_sync(0xffffffffu, kfound, src);
        k = kfound;
        prefix |= dfound << shift;
        mask   |= 0xFFu << shift;
        __syncwarp();
    }
    const float thrv = __uint_as_float(prefix);

#pragma unroll
    for (int i = 0; i < 8; i++) {
        int n = i * 128 + lane * 4;
        float4 vv = *(const float4*)(&v[w][n]);
        float4 o;
        float* vp = &vv.x;
        float* op = &o.x;
#pragma unroll
        for (int jc = 0; jc < 4; jc++) {
            float val = vp[jc];
            float av = fabsf(val);
            float th = theta * (1.0f / (xabs[i * 4 + jc] / 0.1f + 1.0f));
            float st = copysignf(fmaxf(av - th, 0.0f), val);
            op[jc] = (av > thrv) ? val : st;
        }
        *(float4*)(xout + base + n) = o;
    }
}

// ---------------------------------------------------------------------------
// Prep / misc kernels
// ---------------------------------------------------------------------------
__global__ void split_h2_kernel(const float* __restrict__ in,
                                uint32_t* __restrict__ hi2,
                                uint32_t* __restrict__ lo2, size_t npairs)
{
    size_t i = (size_t)blockIdx.x * blockDim.x + threadIdx.x;
    if (i < npairs) {
        float2 v = ((const float2*)in)[i];
        uint32_t h, l;
        h2split(v, h, l);
        hi2[i] = h;
        lo2[i] = l;
    }
}

__global__ void transpose_w_kernel(const float* __restrict__ Win,
                                   float* __restrict__ wt)
{
    __shared__ float tile[32][33];
    int n0 = blockIdx.x * 32;
    int m0 = blockIdx.y * 32;
    int tx = threadIdx.x, ty = threadIdx.y;
    for (int i = ty; i < 32; i += 8)
        tile[i][tx] = Win[(size_t)(m0 + i) * Ndim + n0 + tx];
    __syncthreads();
    for (int i = ty; i < 32; i += 8)
        wt[(size_t)(n0 + i) * Mdim + m0 + tx] = tile[tx][i];
}

__global__ void neg_copy_kernel(const float* __restrict__ src,
                                float* __restrict__ dst, size_t n)
{
    size_t i = ((size_t)blockIdx.x * blockDim.x + threadIdx.x) * 4;
    if (i < n) {
        float4 vq = *(const float4*)(src + i);
        vq.x = -vq.x; vq.y = -vq.y; vq.z = -vq.z; vq.w = -vq.w;
        *(float4*)(dst + i) = vq;
    }
}

__global__ void zero_kernel(float* __restrict__ p, size_t n)
{
    for (size_t i = (size_t)blockIdx.x * blockDim.x + threadIdx.x; i < n;
         i += (size_t)gridDim.x * blockDim.x)
        p[i] = 0.0f;
}

// ---------------------------------------------------------------------------
// Launch
// ---------------------------------------------------------------------------
extern "C" void kernel_launch(void* const* d_in, const int* in_sizes, int n_in,
                              void* d_out, int out_size)
{
    const float* y     = (const float*)d_in[0];
    const float* phi   = (const float*)d_in[1];
    const float* W     = (const float*)d_in[2];
    const float* gamma = (const float*)d_in[3];
    const float* theta = (const float*)d_in[4];
    float* out = (float*)d_out;

    float *xp, *rp, *cp;
    uint32_t *phih2, *phil2, *wth2, *wtl2;
    cudaGetSymbolAddress((void**)&xp,    g_x);
    cudaGetSymbolAddress((void**)&rp,    g_r);
    cudaGetSymbolAddress((void**)&cp,    g_c);
    cudaGetSymbolAddress((void**)&phih2, g_phih2);
    cudaGetSymbolAddress((void**)&phil2, g_phil2);
    cudaGetSymbolAddress((void**)&wth2,  g_wth2);
    cudaGetSymbolAddress((void**)&wtl2,  g_wtl2);

    cudaFuncSetAttribute(gemm_tc<1>, cudaFuncAttributeMaxDynamicSharedMemorySize,
                         GEMM_SMEM);
    cudaFuncSetAttribute(gemm_tc<0>, cudaFuncAttributeMaxDynamicSharedMemorySize,
                         GEMM_SMEM);

    // prep: phi packed split; W^T via fp32 transpose into g_c head, then split
    split_h2_kernel<<<(Mdim * Ndim / 2 + 255) / 256, 256>>>(
        phi, phih2, phil2, (size_t)Mdim * Ndim / 2);
    transpose_w_kernel<<<dim3(Ndim / 32, Mdim / 32), dim3(32, 8)>>>(W, cp);
    split_h2_kernel<<<(Ndim * Mdim / 2 + 255) / 256, 256>>>(
        cp, wth2, wtl2, (size_t)Ndim * Mdim / 2);
    zero_kernel<<<2048, 256>>>(xp, (size_t)Bdim * Ndim);

    for (int it = 0; it < Kiter; it++) {
        // r = x @ phi^T - y  (it 0: x = 0 -> r = -y)
        if (it == 0) {
            neg_copy_kernel<<<(Bdim * Mdim / 4 + 255) / 256, 256>>>(
                y, rp, (size_t)Bdim * Mdim);
        } else {
            gemm_tc<1><<<dim3(Mdim / 128, Bdim / 128), 256, GEMM_SMEM>>>(
                xp, phih2, phil2, rp, y, Ndim, Mdim);
        }
        // c = r @ W  (B operand = W^T packed-split, k-major over M)
        gemm_tc<0><<<dim3(Ndim / 128, Bdim / 128), 256, GEMM_SMEM>>>(
            rp, wth2, wtl2, cp, nullptr, Mdim, Ndim);
        // x = soft_threshold(x - gamma*c, theta*g(|x|), 50)
        float* xout = (it == Kiter - 1) ? out : xp;
        update_kernel<<<Bdim / 8, 256>>>(xp, xout, cp, gamma, theta, it);
    }

    // zero the tail (the two (K,1) zero outputs appended after x)
    long long tail = (long long)out_size - (long long)Ndim * Bdim;
    if (tail > 0)
        zero_kernel<<<1, 256>>>(out + (size_t)Ndim * Bdim, (size_t)tail);
}